// round 6
// baseline (speedup 1.0000x reference)
#include <cuda_runtime.h>
#include <cuda_bf16.h>
#include <math.h>
#include <stdint.h>

#define DM    1024
#define NIMU  72
#define NOUT  864
#define NPAD  896
#define SEQ_MAX 4096
#define KC    64
#define NCH   (DM / KC)     // 16 k-chunks
#define TILEB 16384         // 128 rows x 128B
#define STAGEB (4 * TILEB)  // Ah, Al, Bh, Bl

__device__ __nv_bfloat16 g_xn_hi[SEQ_MAX * DM];
__device__ __nv_bfloat16 g_xn_lo[SEQ_MAX * DM];
__device__ __nv_bfloat16 g_wT_hi[NPAD * DM];   // [n][k] K-major
__device__ __nv_bfloat16 g_wT_lo[NPAD * DM];
__device__ float         g_p[SEQ_MAX * NPAD];
__device__ float         g_osc[SEQ_MAX * NIMU * 8];

// ---------------- helpers ----------------
__device__ __forceinline__ uint32_t smem_u32(const void* p) {
    uint32_t a;
    asm("{ .reg .u64 t; cvta.to.shared.u64 t, %1; cvt.u32.u64 %0, t; }" : "=r"(a) : "l"(p));
    return a;
}
#define SWZ128(o) ((o) ^ (((o) >> 3) & 0x70))

__device__ __forceinline__ void cp16(uint32_t s, const void* g) {
    asm volatile("cp.async.cg.shared.global [%0], [%1], 16;"
                 :: "r"(s), "l"(__cvta_generic_to_global(g)) : "memory");
}
#define CP_COMMIT() asm volatile("cp.async.commit_group;" ::: "memory")
#define CP_WAIT(n)  asm volatile("cp.async.wait_group %0;" :: "n"(n) : "memory")

#define LDSM4(r0, r1, r2, r3, a) \
    asm volatile("ldmatrix.sync.aligned.m8n8.x4.shared.b16 {%0,%1,%2,%3}, [%4];" \
                 : "=r"(r0), "=r"(r1), "=r"(r2), "=r"(r3) : "r"(a))

#define MMA(d, a, b) \
    asm volatile("mma.sync.aligned.m16n8k16.row.col.f32.bf16.bf16.f32 " \
                 "{%0,%1,%2,%3}, {%4,%5,%6,%7}, {%8,%9}, {%0,%1,%2,%3};" \
                 : "+f"((d)[0]), "+f"((d)[1]), "+f"((d)[2]), "+f"((d)[3]) \
                 : "r"((a)[0]), "r"((a)[1]), "r"((a)[2]), "r"((a)[3]), \
                   "r"((b)[0]), "r"((b)[1]))

// ---------------- misc kernels ----------------
__global__ void zero_kernel(float* __restrict__ out, int n) {
    int i = blockIdx.x * blockDim.x + threadIdx.x;
    if (i < n) out[i] = 0.0f;
}

__global__ __launch_bounds__(256) void ln_kernel(const float* __restrict__ x,
                                                 const float* __restrict__ gamma,
                                                 const float* __restrict__ beta) {
    int s = blockIdx.x, tid = threadIdx.x;
    const float4* xr = (const float4*)(x + (size_t)s * DM);
    float4 v = xr[tid];
    float sum = v.x + v.y + v.z + v.w;
    float sq  = v.x*v.x + v.y*v.y + v.z*v.z + v.w*v.w;
#pragma unroll
    for (int o = 16; o > 0; o >>= 1) {
        sum += __shfl_xor_sync(0xffffffffu, sum, o);
        sq  += __shfl_xor_sync(0xffffffffu, sq,  o);
    }
    __shared__ float ssum[8], ssq[8], s_mu, s_rs;
    int wid = tid >> 5, lane = tid & 31;
    if (lane == 0) { ssum[wid] = sum; ssq[wid] = sq; }
    __syncthreads();
    if (tid == 0) {
        float ts = 0.f, tq = 0.f;
#pragma unroll
        for (int i = 0; i < 8; i++) { ts += ssum[i]; tq += ssq[i]; }
        float mu  = ts * (1.0f / DM);
        float var = tq * (1.0f / DM) - mu * mu;
        s_mu = mu; s_rs = rsqrtf(var + 1e-5f);
    }
    __syncthreads();
    float mu = s_mu, rs = s_rs;
    size_t base = (size_t)s * DM + (size_t)tid * 4;
    float xv[4] = {v.x, v.y, v.z, v.w};
#pragma unroll
    for (int j = 0; j < 4; j++) {
        int c = tid * 4 + j;
        float xn = (xv[j] - mu) * rs * gamma[c] + beta[c];
        __nv_bfloat16 hi = __float2bfloat16(xn);
        g_xn_hi[base + j] = hi;
        g_xn_lo[base + j] = __float2bfloat16(xn - __bfloat162float(hi));
    }
}

__global__ void wsplit_kernel(const float* __restrict__ W) {
    int idx = blockIdx.x * blockDim.x + threadIdx.x;
    if (idx >= NPAD * DM) return;
    int n = idx / DM, k = idx - n * DM;
    float w = (n < NOUT) ? W[k * NOUT + n] : 0.0f;
    __nv_bfloat16 hi = __float2bfloat16(w);
    g_wT_hi[idx] = hi;
    g_wT_lo[idx] = __float2bfloat16(w - __bfloat162float(hi));
}

// ---------------- mma.sync 3-split bf16 GEMM: g_p = Xn * W^T ----------------
#define LOAD_STAGE(kc, s) do {                                          \
    uint32_t base_ = sb + (uint32_t)(s) * STAGEB;                       \
    _Pragma("unroll")                                                   \
    for (int i_ = 0; i_ < 4; i_++) {                                    \
        int seg_ = tid + i_ * 256;                                      \
        int rr_ = seg_ >> 3, cc_ = seg_ & 7;                            \
        uint32_t sw_ = SWZ128(rr_ * 128 + cc_ * 16);                    \
        size_t ga_ = (size_t)(bm + rr_) * DM + (kc) * KC + cc_ * 8;     \
        size_t gb_ = (size_t)(bn + rr_) * DM + (kc) * KC + cc_ * 8;     \
        cp16(base_ + sw_,             g_xn_hi + ga_);                   \
        cp16(base_ + 16384 + sw_,     g_xn_lo + ga_);                   \
        cp16(base_ + 32768 + sw_,     g_wT_hi + gb_);                   \
        cp16(base_ + 49152 + sw_,     g_wT_lo + gb_);                   \
    }                                                                   \
    CP_COMMIT();                                                        \
} while (0)

__global__ __launch_bounds__(256) void gemm_kernel() {
    extern __shared__ __align__(1024) char smem[];
    uint32_t sb = smem_u32(smem);
    int tid = threadIdx.x, wid = tid >> 5, lane = tid & 31;
    int bm = blockIdx.x * 128, bn = blockIdx.y * 128;
    int wm = wid & 1, wn = wid >> 1;   // warp tile 64(m) x 32(n)

    LOAD_STAGE(0, 0);

    float acc[4][4][4];
#pragma unroll
    for (int i = 0; i < 4; i++)
#pragma unroll
        for (int j = 0; j < 4; j++)
#pragma unroll
            for (int q = 0; q < 4; q++) acc[i][j][q] = 0.0f;

    // ldmatrix lane address patterns
    int a_m = (lane & 7) + ((lane >> 3) & 1) * 8;
    int a_k = (lane >> 4) * 8;
    int b_n = (lane & 7) + ((lane >> 4) & 1) * 8;
    int b_k = ((lane >> 3) & 1) * 8;

    for (int kc = 0; kc < NCH; kc++) {
        if (kc + 1 < NCH) { LOAD_STAGE(kc + 1, (kc + 1) & 1); CP_WAIT(1); }
        else              { CP_WAIT(0); }
        __syncthreads();
        uint32_t st = sb + (uint32_t)(kc & 1) * STAGEB;
#pragma unroll
        for (int ks = 0; ks < 4; ks++) {
            uint32_t ah[4][4], al[4][4], bh[4][2], bl[4][2];
#pragma unroll
            for (int i = 0; i < 4; i++) {
                uint32_t ad = st + SWZ128((wm * 64 + i * 16 + a_m) * 128 + (ks * 16 + a_k) * 2);
                LDSM4(ah[i][0], ah[i][1], ah[i][2], ah[i][3], ad);
                LDSM4(al[i][0], al[i][1], al[i][2], al[i][3], ad + 16384);
            }
#pragma unroll
            for (int jj = 0; jj < 2; jj++) {
                uint32_t bd = st + 32768 + SWZ128((wn * 32 + jj * 16 + b_n) * 128 + (ks * 16 + b_k) * 2);
                LDSM4(bh[2*jj][0], bh[2*jj][1], bh[2*jj+1][0], bh[2*jj+1][1], bd);
                LDSM4(bl[2*jj][0], bl[2*jj][1], bl[2*jj+1][0], bl[2*jj+1][1], bd + 16384);
            }
#pragma unroll
            for (int i = 0; i < 4; i++)
#pragma unroll
                for (int j = 0; j < 4; j++) {
                    MMA(acc[i][j], ah[i], bh[j]);
                    MMA(acc[i][j], ah[i], bl[j]);
                    MMA(acc[i][j], al[i], bh[j]);
                }
        }
        __syncthreads();
    }

    // epilogue: C frag -> g_p as float2 stores
    int m0 = bm + wm * 64 + (lane >> 2);
    int n0 = bn + wn * 32 + 2 * (lane & 3);
#pragma unroll
    for (int i = 0; i < 4; i++)
#pragma unroll
        for (int j = 0; j < 4; j++) {
            *(float2*)(g_p + (size_t)(m0 + i * 16) * NPAD + n0 + j * 8) =
                make_float2(acc[i][j][0], acc[i][j][1]);
            *(float2*)(g_p + (size_t)(m0 + i * 16 + 8) * NPAD + n0 + j * 8) =
                make_float2(acc[i][j][2], acc[i][j][3]);
        }
}

// ---------------- param transform ----------------
__device__ __forceinline__ float softplusf(float x) {
    return (x > 20.0f) ? x : log1pf(expf(x));
}

__global__ void transform_kernel(const float* __restrict__ bias, float* __restrict__ out, int seq) {
    int t = blockIdx.x * blockDim.x + threadIdx.x;
    if (t >= seq * NIMU) return;
    int s = t / NIMU, imu = t - s * NIMU;
    float p[12];
#pragma unroll
    for (int n = 0; n < 12; n++)
        p[n] = g_p[(size_t)s * NPAD + n * NIMU + imu] + bias[n * NIMU + imu];

    float d1 = softplusf(p[1]);
    float w1 = sqrtf(softplusf(p[0]));
    float d2 = softplusf(p[3]);
    float w2 = sqrtf(softplusf(p[2]));
    float E1 = expf(-0.5f * d1), E2 = expf(-0.5f * d2);
    float sw1, cw1, sw2, cw2, sp1, cp1, sp2, cp2;
    sincosf(w1, &sw1, &cw1);
    sincosf(w2, &sw2, &cw2);
    sincosf(p[6], &sp1, &cp1);
    sincosf(p[7], &sp2, &cp2);

    float4 u = make_float4(E1 * cw1, E1 * sw1, p[4] * sp1, p[4] * cp1);
    float4 v = make_float4(E2 * cw2, E2 * sw2, p[5] * sp2, p[5] * cp2);
    float4* dst = (float4*)(g_osc + (size_t)t * 8);
    dst[0] = u;
    dst[1] = v;

    size_t SL = (size_t)seq, sec = (size_t)NIMU * SL;
    out[1 * sec + (size_t)imu * SL + s] = p[8];
    out[2 * sec + (size_t)imu * SL + s] = softplusf(p[9]);
    out[3 * sec + (size_t)imu * SL + s] = p[10];
    out[4 * sec + (size_t)imu * SL + s] = softplusf(p[11]);
}

// ---------------- oscillator + rotating-accumulator scatter + early exit ----------------
__global__ __launch_bounds__(256) void osc_kernel(float* __restrict__ out, int seq, int tsteps) {
    int chunks = seq >> 8;
    int imu = blockIdx.x / chunks;
    int ch  = blockIdx.x - imu * chunks;
    int lane = threadIdx.x & 31;
    int B = ch * 256 + (threadIdx.x >> 5) * 32;
    int s = B + lane;

    const float4* oc = (const float4*)(g_osc + ((size_t)s * NIMU + imu) * 8);
    float4 u = oc[0], v = oc[1];
    float a1 = u.x, b1 = u.y, S1 = u.z, C1 = u.w;
    float a2 = v.x, b2 = v.y, S2 = v.z, C2 = v.w;
    float nb1 = -b1, nb2 = -b2;
    // tail-sum bound factor: sum_{t>t0} amp*E^(t-t0) <= amp * E/(1-E)
    float E1 = sqrtf(a1 * a1 + b1 * b1);
    float E2 = sqrtf(a2 * a2 + b2 * b2);
    float f1 = E1 / fmaxf(1.0f - E1, 1e-6f);
    float f2 = E2 / fmaxf(1.0f - E2, 1e-6f);
    float acc = 0.0f;
    float* kout = out + (size_t)imu * seq;

    int t = 0;
    while (t < tsteps) {
        int e = t + 20 < tsteps ? t + 20 : tsteps;
#pragma unroll 4
        for (; t < e; t++) {
            acc += S1;
            acc += S2;
            float Sn1 = fmaf(a1, S1, b1 * C1);
            C1 = fmaf(nb1, S1, a1 * C1);
            S1 = Sn1;
            float Sn2 = fmaf(a2, S2, b2 * C2);
            C2 = fmaf(nb2, S2, a2 * C2);
            S2 = Sn2;
            int pos = B + t;
            if (lane == 0) {
                if (pos < seq) atomicAdd(kout + pos, acc);
                acc = 0.0f;
            }
            acc = __shfl_sync(0xffffffffu, acc, (lane + 1) & 31);
        }
        float m1 = (fabsf(S1) + fabsf(C1)) * f1;
        float m2 = (fabsf(S2) + fabsf(C2)) * f2;
        if (!__any_sync(0xffffffffu, fmaxf(m1, m2) > 1e-7f)) break;
    }
    // drain: lane l holds completed partial for position B + t + l
    int pos = B + t + lane;
    if (pos < seq && acc != 0.0f) atomicAdd(kout + pos, acc);
}

extern "C" void kernel_launch(void* const* d_in, const int* in_sizes, int n_in,
                              void* d_out, int out_size) {
    const float* x     = (const float*)d_in[0];
    const float* gamma = (const float*)d_in[1];
    const float* beta  = (const float*)d_in[2];
    const float* W     = (const float*)d_in[3];
    const float* b     = (const float*)d_in[4];
    float* out = (float*)d_out;

    int seq = in_sizes[0] / DM;
    int tsteps = seq < 300 ? seq : 300;
    int gemm_smem = 2 * STAGEB;   // 128 KB

    cudaFuncSetAttribute(gemm_kernel, cudaFuncAttributeMaxDynamicSharedMemorySize, gemm_smem);

    zero_kernel<<<(NIMU * seq + 255) / 256, 256>>>(out, NIMU * seq);
    ln_kernel<<<seq, 256>>>(x, gamma, beta);
    wsplit_kernel<<<(NPAD * DM + 255) / 256, 256>>>(W);
    dim3 gg(seq / 128, NPAD / 128);
    gemm_kernel<<<gg, 256, gemm_smem>>>();
    transform_kernel<<<(seq * NIMU + 255) / 256, 256>>>(b, out, seq);
    osc_kernel<<<NIMU * (seq / 256), 256>>>(out, seq, tsteps);
}

// round 7
// speedup vs baseline: 1.5011x; 1.5011x over previous
#include <cuda_runtime.h>
#include <cuda_bf16.h>
#include <math.h>
#include <stdint.h>

#define DM    1024
#define NIMU  72
#define NOUT  864
#define NPAD  896
#define SEQ_MAX 4096
#define KC    64
#define NCH   (DM / KC)
#define TILEB 16384
#define STAGEB (4 * TILEB)

__device__ __nv_bfloat16 g_xn_hi[SEQ_MAX * DM];
__device__ __nv_bfloat16 g_xn_lo[SEQ_MAX * DM];
__device__ __nv_bfloat16 g_wT_hi[NPAD * DM];
__device__ __nv_bfloat16 g_wT_lo[NPAD * DM];
__device__ float         g_p[SEQ_MAX * NPAD];
__device__ float         g_osc[SEQ_MAX * NIMU * 8];

__device__ __forceinline__ uint32_t smem_u32(const void* p) {
    uint32_t a;
    asm("{ .reg .u64 t; cvta.to.shared.u64 t, %1; cvt.u32.u64 %0, t; }" : "=r"(a) : "l"(p));
    return a;
}
#define SWZ128(o) ((o) ^ (((o) >> 3) & 0x70))

__device__ __forceinline__ void cp16(uint32_t s, const void* g) {
    asm volatile("cp.async.cg.shared.global [%0], [%1], 16;"
                 :: "r"(s), "l"(__cvta_generic_to_global(g)) : "memory");
}
#define CP_COMMIT() asm volatile("cp.async.commit_group;" ::: "memory")
#define CP_WAIT(n)  asm volatile("cp.async.wait_group %0;" :: "n"(n) : "memory")

#define LDSM4(r0, r1, r2, r3, a) \
    asm volatile("ldmatrix.sync.aligned.m8n8.x4.shared.b16 {%0,%1,%2,%3}, [%4];" \
                 : "=r"(r0), "=r"(r1), "=r"(r2), "=r"(r3) : "r"(a))

#define MMA(d, a, b) \
    asm volatile("mma.sync.aligned.m16n8k16.row.col.f32.bf16.bf16.f32 " \
                 "{%0,%1,%2,%3}, {%4,%5,%6,%7}, {%8,%9}, {%0,%1,%2,%3};" \
                 : "+f"((d)[0]), "+f"((d)[1]), "+f"((d)[2]), "+f"((d)[3]) \
                 : "r"((a)[0]), "r"((a)[1]), "r"((a)[2]), "r"((a)[3]), \
                   "r"((b)[0]), "r"((b)[1]))

// ---------------- LayerNorm + split ----------------
__global__ __launch_bounds__(256) void ln_kernel(const float* __restrict__ x,
                                                 const float* __restrict__ gamma,
                                                 const float* __restrict__ beta) {
    int s = blockIdx.x, tid = threadIdx.x;
    const float4* xr = (const float4*)(x + (size_t)s * DM);
    float4 v = xr[tid];
    float sum = v.x + v.y + v.z + v.w;
    float sq  = v.x*v.x + v.y*v.y + v.z*v.z + v.w*v.w;
#pragma unroll
    for (int o = 16; o > 0; o >>= 1) {
        sum += __shfl_xor_sync(0xffffffffu, sum, o);
        sq  += __shfl_xor_sync(0xffffffffu, sq,  o);
    }
    __shared__ float ssum[8], ssq[8], s_mu, s_rs;
    int wid = tid >> 5, lane = tid & 31;
    if (lane == 0) { ssum[wid] = sum; ssq[wid] = sq; }
    __syncthreads();
    if (tid == 0) {
        float ts = 0.f, tq = 0.f;
#pragma unroll
        for (int i = 0; i < 8; i++) { ts += ssum[i]; tq += ssq[i]; }
        float mu  = ts * (1.0f / DM);
        float var = tq * (1.0f / DM) - mu * mu;
        s_mu = mu; s_rs = rsqrtf(var + 1e-5f);
    }
    __syncthreads();
    float mu = s_mu, rs = s_rs;
    size_t base = (size_t)s * DM + (size_t)tid * 4;
    float xv[4] = {v.x, v.y, v.z, v.w};
#pragma unroll
    for (int j = 0; j < 4; j++) {
        int c = tid * 4 + j;
        float xn = (xv[j] - mu) * rs * gamma[c] + beta[c];
        __nv_bfloat16 hi = __float2bfloat16(xn);
        g_xn_hi[base + j] = hi;
        g_xn_lo[base + j] = __float2bfloat16(xn - __bfloat162float(hi));
    }
}

__global__ void wsplit_kernel(const float* __restrict__ W) {
    int idx = blockIdx.x * blockDim.x + threadIdx.x;
    if (idx >= NPAD * DM) return;
    int n = idx / DM, k = idx - n * DM;
    float w = (n < NOUT) ? W[k * NOUT + n] : 0.0f;
    __nv_bfloat16 hi = __float2bfloat16(w);
    g_wT_hi[idx] = hi;
    g_wT_lo[idx] = __float2bfloat16(w - __bfloat162float(hi));
}

// ---------------- mma.sync 3-split bf16 GEMM, 512 threads ----------------
#define LOAD_STAGE(kc, s) do {                                          \
    uint32_t base_ = sb + (uint32_t)(s) * STAGEB;                       \
    _Pragma("unroll")                                                   \
    for (int i_ = 0; i_ < 2; i_++) {                                    \
        int seg_ = tid + i_ * 512;                                      \
        int rr_ = seg_ >> 3, cc_ = seg_ & 7;                            \
        uint32_t sw_ = SWZ128(rr_ * 128 + cc_ * 16);                    \
        size_t ga_ = (size_t)(bm + rr_) * DM + (kc) * KC + cc_ * 8;     \
        size_t gb_ = (size_t)(bn + rr_) * DM + (kc) * KC + cc_ * 8;     \
        cp16(base_ + sw_,             g_xn_hi + ga_);                   \
        cp16(base_ + 16384 + sw_,     g_xn_lo + ga_);                   \
        cp16(base_ + 32768 + sw_,     g_wT_hi + gb_);                   \
        cp16(base_ + 49152 + sw_,     g_wT_lo + gb_);                   \
    }                                                                   \
    CP_COMMIT();                                                        \
} while (0)

__global__ __launch_bounds__(512) void gemm_kernel() {
    extern __shared__ __align__(1024) char smem[];
    uint32_t sb = smem_u32(smem);
    int tid = threadIdx.x, wid = tid >> 5, lane = tid & 31;
    int bm = blockIdx.x * 128, bn = blockIdx.y * 128;
    int wm = wid & 3, wn = wid >> 2;   // 4x4 warp grid, 32x32 warp tiles

    LOAD_STAGE(0, 0);

    float acc[2][4][4];
#pragma unroll
    for (int i = 0; i < 2; i++)
#pragma unroll
        for (int j = 0; j < 4; j++)
#pragma unroll
            for (int q = 0; q < 4; q++) acc[i][j][q] = 0.0f;

    int a_m = (lane & 7) + ((lane >> 3) & 1) * 8;
    int a_k = (lane >> 4) * 8;
    int b_n = (lane & 7) + ((lane >> 4) & 1) * 8;
    int b_k = ((lane >> 3) & 1) * 8;

    for (int kc = 0; kc < NCH; kc++) {
        if (kc + 1 < NCH) { LOAD_STAGE(kc + 1, (kc + 1) & 1); CP_WAIT(1); }
        else              { CP_WAIT(0); }
        __syncthreads();
        uint32_t st = sb + (uint32_t)(kc & 1) * STAGEB;
#pragma unroll
        for (int ks = 0; ks < 4; ks++) {
            uint32_t ah[2][4], al[2][4], bh[4][2], bl[4][2];
#pragma unroll
            for (int i = 0; i < 2; i++) {
                uint32_t ad = st + SWZ128((wm * 32 + i * 16 + a_m) * 128 + (ks * 16 + a_k) * 2);
                LDSM4(ah[i][0], ah[i][1], ah[i][2], ah[i][3], ad);
                LDSM4(al[i][0], al[i][1], al[i][2], al[i][3], ad + 16384);
            }
#pragma unroll
            for (int jj = 0; jj < 2; jj++) {
                uint32_t bd = st + 32768 + SWZ128((wn * 32 + jj * 16 + b_n) * 128 + (ks * 16 + b_k) * 2);
                LDSM4(bh[2*jj][0], bh[2*jj][1], bh[2*jj+1][0], bh[2*jj+1][1], bd);
                LDSM4(bl[2*jj][0], bl[2*jj][1], bl[2*jj+1][0], bl[2*jj+1][1], bd + 16384);
            }
#pragma unroll
            for (int i = 0; i < 2; i++)
#pragma unroll
                for (int j = 0; j < 4; j++) {
                    MMA(acc[i][j], ah[i], bh[j]);
                    MMA(acc[i][j], ah[i], bl[j]);
                    MMA(acc[i][j], al[i], bh[j]);
                }
        }
        __syncthreads();
    }

    int m0 = bm + wm * 32 + (lane >> 2);
    int n0 = bn + wn * 32 + 2 * (lane & 3);
#pragma unroll
    for (int i = 0; i < 2; i++)
#pragma unroll
        for (int j = 0; j < 4; j++) {
            *(float2*)(g_p + (size_t)(m0 + i * 16) * NPAD + n0 + j * 8) =
                make_float2(acc[i][j][0], acc[i][j][1]);
            *(float2*)(g_p + (size_t)(m0 + i * 16 + 8) * NPAD + n0 + j * 8) =
                make_float2(acc[i][j][2], acc[i][j][3]);
        }
}

// ---------------- param transform (also zeroes kinematics section) ----------------
__device__ __forceinline__ float softplusf(float x) {
    return (x > 20.0f) ? x : log1pf(expf(x));
}

__global__ void transform_kernel(const float* __restrict__ bias, float* __restrict__ out, int seq) {
    int t = blockIdx.x * blockDim.x + threadIdx.x;
    if (t >= seq * NIMU) return;
    int s = t / NIMU, imu = t - s * NIMU;
    float p[12];
#pragma unroll
    for (int n = 0; n < 12; n++)
        p[n] = g_p[(size_t)s * NPAD + n * NIMU + imu] + bias[n * NIMU + imu];

    float d1 = softplusf(p[1]);
    float w1 = sqrtf(softplusf(p[0]));
    float d2 = softplusf(p[3]);
    float w2 = sqrtf(softplusf(p[2]));
    float E1 = expf(-0.5f * d1), E2 = expf(-0.5f * d2);
    float sw1, cw1, sw2, cw2, sp1, cp1, sp2, cp2;
    sincosf(w1, &sw1, &cw1);
    sincosf(w2, &sw2, &cw2);
    sincosf(p[6], &sp1, &cp1);
    sincosf(p[7], &sp2, &cp2);

    float4 u = make_float4(E1 * cw1, E1 * sw1, p[4] * sp1, p[4] * cp1);
    float4 v = make_float4(E2 * cw2, E2 * sw2, p[5] * sp2, p[5] * cp2);
    float4* dst = (float4*)(g_osc + (size_t)t * 8);
    dst[0] = u;
    dst[1] = v;

    size_t SL = (size_t)seq, sec = (size_t)NIMU * SL;
    out[0 * sec + (size_t)imu * SL + s] = 0.0f;                 // zero kinematics
    out[1 * sec + (size_t)imu * SL + s] = p[8];
    out[2 * sec + (size_t)imu * SL + s] = softplusf(p[9]);
    out[3 * sec + (size_t)imu * SL + s] = p[10];
    out[4 * sec + (size_t)imu * SL + s] = softplusf(p[11]);
}

// ---------------- oscillator + rotating-accumulator scatter (R3 form) ----------------
__global__ __launch_bounds__(256) void osc_kernel(float* __restrict__ out, int seq, int tsteps) {
    int chunks = seq >> 8;
    int imu = blockIdx.x / chunks;
    int ch  = blockIdx.x - imu * chunks;
    int lane = threadIdx.x & 31;
    int B = ch * 256 + (threadIdx.x >> 5) * 32;
    int s = B + lane;

    const float4* oc = (const float4*)(g_osc + ((size_t)s * NIMU + imu) * 8);
    float4 u = oc[0], v = oc[1];
    float a1 = u.x, b1 = u.y, S1 = u.z, C1 = u.w;
    float a2 = v.x, b2 = v.y, S2 = v.z, C2 = v.w;
    float nb1 = -b1, nb2 = -b2;
    float acc = 0.0f;
    float* kout = out + (size_t)imu * seq;

#pragma unroll 4
    for (int t = 0; t < tsteps; t++) {
        acc += S1;
        acc += S2;
        float Sn1 = fmaf(a1, S1, b1 * C1);
        C1 = fmaf(nb1, S1, a1 * C1);
        S1 = Sn1;
        float Sn2 = fmaf(a2, S2, b2 * C2);
        C2 = fmaf(nb2, S2, a2 * C2);
        S2 = Sn2;
        int pos = B + t;
        if (lane == 0) {
            if (pos < seq) atomicAdd(kout + pos, acc);
            acc = 0.0f;
        }
        acc = __shfl_sync(0xffffffffu, acc, (lane + 1) & 31);
    }
    int pos = B + tsteps + lane;
    if (pos < seq && acc != 0.0f) atomicAdd(kout + pos, acc);
}

extern "C" void kernel_launch(void* const* d_in, const int* in_sizes, int n_in,
                              void* d_out, int out_size) {
    const float* x     = (const float*)d_in[0];
    const float* gamma = (const float*)d_in[1];
    const float* beta  = (const float*)d_in[2];
    const float* W     = (const float*)d_in[3];
    const float* b     = (const float*)d_in[4];
    float* out = (float*)d_out;

    int seq = in_sizes[0] / DM;
    int tsteps = seq < 300 ? seq : 300;
    int gemm_smem = 2 * STAGEB;   // 128 KB

    cudaFuncSetAttribute(gemm_kernel, cudaFuncAttributeMaxDynamicSharedMemorySize, gemm_smem);

    ln_kernel<<<seq, 256>>>(x, gamma, beta);
    wsplit_kernel<<<(NPAD * DM + 255) / 256, 256>>>(W);
    dim3 gg(seq / 128, NPAD / 128);
    gemm_kernel<<<gg, 512, gemm_smem>>>();
    transform_kernel<<<(seq * NIMU + 255) / 256, 256>>>(b, out, seq);
    osc_kernel<<<NIMU * (seq / 256), 256>>>(out, seq, tsteps);
}